// round 1
// baseline (speedup 1.0000x reference)
#include <cuda_runtime.h>

#define BB 64
#define SS 1024
#define DD 1024
#define VV 1024

// ---------------- scratch (no allocation allowed) ----------------
__device__ float g_w1  [BB * SS];
__device__ float g_w2  [BB * SS];
__device__ float g_w3  [BB * SS];
__device__ float g_wsum[BB * SS];
__device__ float g_accv[BB * VV];
__device__ float g_accs[BB * DD];
__device__ float g_gs  [BB * DD];
__device__ float g_ho  [BB * DD];
__device__ float g_hf  [BB * DD];

// ---------------- K1: w1[b,:] = mask[b] * step[b, qidx[b], :] ----------------
__global__ void k_gather(const float* __restrict__ step,
                         const int* __restrict__ qidx,
                         const float* __restrict__ qmask) {
    int b = blockIdx.x;
    int q = qidx[b];
    float m = qmask[b];
    const float* row = step + ((size_t)b * SS + (size_t)q) * SS;
    for (int t = threadIdx.x; t < SS; t += blockDim.x)
        g_w1[b * SS + t] = m * row[t];
}

// ---------------- batched matvec: y[b,t] += sum_s x[b,s] * M[b,s,t] ----------
// grid = (NCHUNK=16, B), block = 256.  Each CTA handles 64 rows (s) and all
// 1024 columns t (4 per thread, float4). Partial sums combined via atomicAdd.
__global__ void __launch_bounds__(256) k_matvec(const float* __restrict__ M,
                                                const float* __restrict__ x,
                                                float* __restrict__ y) {
    const int b  = blockIdx.y;
    const int s0 = blockIdx.x * 64;
    const float* Mb = M + (size_t)b * SS * SS + (size_t)s0 * SS;
    const float* xb = x + b * SS + s0;
    const int t0 = threadIdx.x * 4;

    float a0 = 0.f, a1 = 0.f, a2 = 0.f, a3 = 0.f;
#pragma unroll 4
    for (int s = 0; s < 64; ++s) {
        float xs = __ldg(xb + s);
        float4 m = *reinterpret_cast<const float4*>(Mb + (size_t)s * SS + t0);
        a0 += xs * m.x;
        a1 += xs * m.y;
        a2 += xs * m.z;
        a3 += xs * m.w;
    }
    float* yp = y + b * SS + t0;
    atomicAdd(yp + 0, a0);
    atomicAdd(yp + 1, a1);
    atomicAdd(yp + 2, a2);
    atomicAdd(yp + 3, a3);
}

// ---------------- K4: w_sum = onehot + w1 + w2 + w3 ----------------
__global__ void k_wsum(const int* __restrict__ qidx,
                       const float* __restrict__ qmask) {
    int b = blockIdx.x;
    int q = qidx[b];
    float m = qmask[b];
    for (int t = threadIdx.x; t < SS; t += blockDim.x) {
        int i = b * SS + t;
        float v = g_w1[i] + g_w2[i] + g_w3[i];
        if (t == q) v += m;
        g_wsum[i] = v;
    }
}

// ---------------- small GEMM: C[64,N] = act(A[64,K] @ W[K,N] + bias) + resid -
// M = 64 (full), BN = 32, BK = 32. grid = N/32, block = 256.
__device__ __forceinline__ float gelu_tanh(float x) {
    float x3 = x * x * x;
    return 0.5f * x * (1.0f + tanhf(0.7978845608028654f * (x + 0.044715f * x3)));
}

template <int ACT>  // 0 = identity, 1 = gelu
__global__ void __launch_bounds__(256) k_gemm(const float* __restrict__ A,
                                              const float* __restrict__ W,
                                              const float* __restrict__ bias,
                                              const float* __restrict__ resid,
                                              float* __restrict__ C,
                                              int K, int N) {
    __shared__ float As[32][64 + 1];   // As[k][m]
    __shared__ float Ws[32][32 + 1];   // Ws[k][n]

    const int tid = threadIdx.x;
    const int n0  = blockIdx.x * 32;
    const int c   = tid & 31;        // local n
    const int rg  = tid >> 5;        // 0..7, rows rg, rg+8, ..., rg+56

    float acc[8];
#pragma unroll
    for (int i = 0; i < 8; ++i) acc[i] = 0.f;

    for (int k0 = 0; k0 < K; k0 += 32) {
        // load A tile: 64x32 elems, 8 per thread, coalesced over k
#pragma unroll
        for (int i = 0; i < 8; ++i) {
            int lin = tid + i * 256;
            int m = lin >> 5;
            int k = lin & 31;
            As[k][m] = A[m * K + k0 + k];
        }
        // load W tile: 32x32 elems, 4 per thread, coalesced over n
#pragma unroll
        for (int i = 0; i < 4; ++i) {
            int lin = tid + i * 256;
            int k = lin >> 5;
            int n = lin & 31;
            Ws[k][n] = W[(size_t)(k0 + k) * N + n0 + n];
        }
        __syncthreads();
#pragma unroll
        for (int k = 0; k < 32; ++k) {
            float wv = Ws[k][c];
#pragma unroll
            for (int i = 0; i < 8; ++i)
                acc[i] += As[k][rg + 8 * i] * wv;
        }
        __syncthreads();
    }

    const int n = n0 + c;
    float bv = (bias != nullptr) ? bias[n] : 0.f;
#pragma unroll
    for (int i = 0; i < 8; ++i) {
        int m = rg + 8 * i;
        float v = acc[i] + bv;
        if (ACT == 1) v = gelu_tanh(v);
        if (resid != nullptr) v += resid[m * N + n];
        C[m * N + n] = v;
    }
}

// ---------------- launch ----------------
extern "C" void kernel_launch(void* const* d_in, const int* in_sizes, int n_in,
                              void* d_out, int out_size) {
    const float* map_memory  = (const float*)d_in[0];
    const float* step_memory = (const float*)d_in[1];
    const int*   query_idx   = (const int*)  d_in[2];
    const float* query_mask  = (const float*)d_in[3];
    const float* symbol_bank = (const float*)d_in[4];
    const float* value_bank  = (const float*)d_in[5];
    const float* Wo1 = (const float*)d_in[6];
    const float* bo1 = (const float*)d_in[7];
    const float* Wo2 = (const float*)d_in[8];
    const float* bo2 = (const float*)d_in[9];
    const float* Wf1 = (const float*)d_in[10];
    const float* bf1 = (const float*)d_in[11];
    const float* Wf2 = (const float*)d_in[12];
    const float* bf2 = (const float*)d_in[13];
    float* out = (float*)d_out;

    float *pw1, *pw2, *pw3, *pwsum, *paccv, *paccs, *pgs, *pho, *phf;
    cudaGetSymbolAddress((void**)&pw1,   g_w1);
    cudaGetSymbolAddress((void**)&pw2,   g_w2);
    cudaGetSymbolAddress((void**)&pw3,   g_w3);
    cudaGetSymbolAddress((void**)&pwsum, g_wsum);
    cudaGetSymbolAddress((void**)&paccv, g_accv);
    cudaGetSymbolAddress((void**)&paccs, g_accs);
    cudaGetSymbolAddress((void**)&pgs,   g_gs);
    cudaGetSymbolAddress((void**)&pho,   g_ho);
    cudaGetSymbolAddress((void**)&phf,   g_hf);

    // zero the atomic-accumulated buffers (every call: graph replays reuse them)
    cudaMemsetAsync(pw2,   0, BB * SS * sizeof(float));
    cudaMemsetAsync(pw3,   0, BB * SS * sizeof(float));
    cudaMemsetAsync(paccv, 0, BB * VV * sizeof(float));

    // walk chain
    k_gather<<<BB, 256>>>(step_memory, query_idx, query_mask);
    dim3 mg(16, BB);
    k_matvec<<<mg, 256>>>(step_memory, pw1, pw2);   // w2 = w1 @ step
    k_matvec<<<mg, 256>>>(step_memory, pw2, pw3);   // w3 = w2 @ step
    k_wsum<<<BB, 256>>>(query_idx, query_mask);     // wsum = onehot+w1+w2+w3
    k_matvec<<<mg, 256>>>(map_memory, pwsum, paccv); // acc_values = wsum @ map

    // projections + heads (all 64x1024x1024 fp32 GEMMs)
    k_gemm<0><<<32, 256>>>(pwsum, symbol_bank, nullptr, nullptr, paccs, SS, DD); // acc_symbols
    k_gemm<0><<<32, 256>>>(paccv, value_bank,  nullptr, paccs,   pgs,   VV, DD); // graph_state
    k_gemm<1><<<32, 256>>>(pgs,   Wo1, bo1, nullptr, pho, DD, DD);               // gelu(gs@Wo1+bo1)
    k_gemm<0><<<32, 256>>>(pho,   Wo2, bo2, nullptr, out, DD, VV);               // logits
    k_gemm<1><<<32, 256>>>(pgs,   Wf1, bf1, nullptr, phf, DD, DD);               // gelu(gs@Wf1+bf1)
    k_gemm<0><<<32, 256>>>(phf,   Wf2, bf2, nullptr, out + BB * VV, DD, DD);     // feedback
}

// round 2
// speedup vs baseline: 3.5553x; 3.5553x over previous
#include <cuda_runtime.h>

#define BB 64
#define SS 1024
#define DD 1024
#define VV 1024

// ---------------- scratch (no allocation allowed) ----------------
// zeroed-every-call region (atomic accumulation targets), one contiguous memset
//   [0]      w2    (64K floats)
//   [64K]    w3    (64K)
//   [128K]   accv  (64K)
//   [192K]   gs    (64K)
//   [256K]   hpre  (128K)  -> [64][2048] (ho_pre | hf_pre)
__device__ float g_zbuf[BB * SS * 4 + BB * 2048];
// non-zeroed scratch: w1 (64K), wsum (64K), h (128K)
__device__ float g_buf[BB * SS * 2 + BB * 2048];

#define OFF_W2   0
#define OFF_W3   (BB * SS)
#define OFF_ACCV (BB * SS * 2)
#define OFF_GS   (BB * SS * 3)
#define OFF_HPRE (BB * SS * 4)

#define OFF_W1   0
#define OFF_WSUM (BB * SS)
#define OFF_H    (BB * SS * 2)

// ---------------- K1: w1[b,:] = mask[b] * step[b, qidx[b], :] ----------------
__global__ void k_gather(const float* __restrict__ step,
                         const int* __restrict__ qidx,
                         const float* __restrict__ qmask) {
    int b = blockIdx.x;
    int q = qidx[b];
    float m = qmask[b];
    const float* row = step + ((size_t)b * SS + (size_t)q) * SS;
    float* w1 = g_buf + OFF_W1;
    for (int t = threadIdx.x; t < SS; t += blockDim.x)
        w1[b * SS + t] = m * row[t];
}

// ---------------- batched matvec: y[b,t] += sum_s x[b,s] * M[b,s,t] ----------
// grid = (8 s-chunks, B), block = 256.  Each CTA handles 128 rows (s), all
// 1024 cols t (float4 per thread). Partial sums combined via atomicAdd.
__global__ void __launch_bounds__(256) k_matvec(const float* __restrict__ M,
                                                const float* __restrict__ x,
                                                float* __restrict__ y) {
    const int b  = blockIdx.y;
    const int s0 = blockIdx.x * 128;
    const float* Mb = M + (size_t)b * SS * SS + (size_t)s0 * SS;
    const float* xb = x + b * SS + s0;
    const int t0 = threadIdx.x * 4;

    float a0 = 0.f, a1 = 0.f, a2 = 0.f, a3 = 0.f;
#pragma unroll 8
    for (int s = 0; s < 128; ++s) {
        float xs = __ldg(xb + s);
        float4 m = *reinterpret_cast<const float4*>(Mb + (size_t)s * SS + t0);
        a0 += xs * m.x;
        a1 += xs * m.y;
        a2 += xs * m.z;
        a3 += xs * m.w;
    }
    float* yp = y + b * SS + t0;
    atomicAdd(yp + 0, a0);
    atomicAdd(yp + 1, a1);
    atomicAdd(yp + 2, a2);
    atomicAdd(yp + 3, a3);
}

// ---------------- wsum = onehot + w1 + w2 + w3 ----------------
__global__ void k_wsum(const int* __restrict__ qidx,
                       const float* __restrict__ qmask) {
    int i = blockIdx.x * blockDim.x + threadIdx.x;   // 0..65535
    int b = i >> 10;
    int t = i & 1023;
    float v = g_buf[OFF_W1 + i] + g_zbuf[OFF_W2 + i] + g_zbuf[OFF_W3 + i];
    if (t == qidx[b]) v += qmask[b];
    g_buf[OFF_WSUM + i] = v;
}

// ---------------- split-K GEMM with z-paired operands ----------------
// C[64,1024-per-z] += A[64,Ktot] @ W[Ktot,1024]  (atomic accumulate)
// grid = (16 n-blocks, KSPLIT, 2), block = 256. BM=64 BN=64 BK=16, 4x4/thread.
template <int KSPLIT>
__global__ void __launch_bounds__(256) k_gemm(
    const float* __restrict__ A0, const float* __restrict__ A1,
    const float* __restrict__ W0, const float* __restrict__ W1,
    float* __restrict__ C0, float* __restrict__ C1,
    int lda, int ldc, int Ktot)
{
    const float* A = blockIdx.z ? A1 : A0;
    const float* W = blockIdx.z ? W1 : W0;
    float*       C = blockIdx.z ? C1 : C0;

    const int n0 = blockIdx.x * 64;
    const int kchunk = Ktot / KSPLIT;
    const int k0 = blockIdx.y * kchunk;

    __shared__ float As[16][68];   // [k][m], stride 68 keeps float4 alignment
    __shared__ float Ws[16][64];   // [k][n]

    const int tid = threadIdx.x;
    const int tx = tid & 15;       // n / 4
    const int ty = tid >> 4;       // m / 4

    float acc[4][4] = {};

    const int lm = tid >> 2;            // 0..63 (A-load row)
    const int lk = (tid & 3) * 4;       // A-load k quad
    const int wk = tid >> 4;            // 0..15 (W-load row)
    const int wn = (tid & 15) * 4;      // W-load n quad

    for (int kt = k0; kt < k0 + kchunk; kt += 16) {
        float4 a = *reinterpret_cast<const float4*>(A + (size_t)lm * lda + kt + lk);
        As[lk + 0][lm] = a.x;
        As[lk + 1][lm] = a.y;
        As[lk + 2][lm] = a.z;
        As[lk + 3][lm] = a.w;
        *reinterpret_cast<float4*>(&Ws[wk][wn]) =
            *reinterpret_cast<const float4*>(W + (size_t)(kt + wk) * 1024 + n0 + wn);
        __syncthreads();
#pragma unroll
        for (int k = 0; k < 16; ++k) {
            float4 av = *reinterpret_cast<const float4*>(&As[k][ty * 4]);
            float4 bv = *reinterpret_cast<const float4*>(&Ws[k][tx * 4]);
            acc[0][0] += av.x * bv.x; acc[0][1] += av.x * bv.y;
            acc[0][2] += av.x * bv.z; acc[0][3] += av.x * bv.w;
            acc[1][0] += av.y * bv.x; acc[1][1] += av.y * bv.y;
            acc[1][2] += av.y * bv.z; acc[1][3] += av.y * bv.w;
            acc[2][0] += av.z * bv.x; acc[2][1] += av.z * bv.y;
            acc[2][2] += av.z * bv.z; acc[2][3] += av.z * bv.w;
            acc[3][0] += av.w * bv.x; acc[3][1] += av.w * bv.y;
            acc[3][2] += av.w * bv.z; acc[3][3] += av.w * bv.w;
        }
        __syncthreads();
    }

#pragma unroll
    for (int i = 0; i < 4; ++i) {
        int m = ty * 4 + i;
#pragma unroll
        for (int j = 0; j < 4; ++j) {
            int n = n0 + tx * 4 + j;
            atomicAdd(&C[(size_t)m * ldc + n], acc[i][j]);
        }
    }
}

// ---------------- gelu+bias epilogue on hpre -> h ----------------
__device__ __forceinline__ float gelu_tanh(float x) {
    float x3 = x * x * x;
    return 0.5f * x * (1.0f + tanhf(0.7978845608028654f * (x + 0.044715f * x3)));
}

__global__ void k_gelu(const float* __restrict__ bo1,
                       const float* __restrict__ bf1) {
    int i = blockIdx.x * blockDim.x + threadIdx.x;   // 0..131071
    int n = i & 2047;
    float b = (n < 1024) ? bo1[n] : bf1[n - 1024];
    g_buf[OFF_H + i] = gelu_tanh(g_zbuf[OFF_HPRE + i] + b);
}

// ---------------- final bias add on d_out ----------------
__global__ void k_bias(float* __restrict__ out,
                       const float* __restrict__ bo2,
                       const float* __restrict__ bf2) {
    int i = blockIdx.x * blockDim.x + threadIdx.x;   // 0..131071
    int n = i & 1023;
    out[i] += (i < BB * VV) ? bo2[n] : bf2[n];
}

// ---------------- launch ----------------
extern "C" void kernel_launch(void* const* d_in, const int* in_sizes, int n_in,
                              void* d_out, int out_size) {
    const float* map_memory  = (const float*)d_in[0];
    const float* step_memory = (const float*)d_in[1];
    const int*   query_idx   = (const int*)  d_in[2];
    const float* query_mask  = (const float*)d_in[3];
    const float* symbol_bank = (const float*)d_in[4];
    const float* value_bank  = (const float*)d_in[5];
    const float* Wo1 = (const float*)d_in[6];
    const float* bo1 = (const float*)d_in[7];
    const float* Wo2 = (const float*)d_in[8];
    const float* bo2 = (const float*)d_in[9];
    const float* Wf1 = (const float*)d_in[10];
    const float* bf1 = (const float*)d_in[11];
    const float* Wf2 = (const float*)d_in[12];
    const float* bf2 = (const float*)d_in[13];
    float* out = (float*)d_out;

    float *zbuf, *buf;
    cudaGetSymbolAddress((void**)&zbuf, g_zbuf);
    cudaGetSymbolAddress((void**)&buf,  g_buf);

    float* pw1   = buf  + OFF_W1;
    float* pwsum = buf  + OFF_WSUM;
    float* ph    = buf  + OFF_H;
    float* pw2   = zbuf + OFF_W2;
    float* pw3   = zbuf + OFF_W3;
    float* paccv = zbuf + OFF_ACCV;
    float* pgs   = zbuf + OFF_GS;
    float* phpre = zbuf + OFF_HPRE;

    // zero all atomic-accumulation targets (one contiguous region) + d_out
    cudaMemsetAsync(zbuf, 0, (BB * SS * 4 + BB * 2048) * sizeof(float));
    cudaMemsetAsync(out,  0, (size_t)BB * 2048 * sizeof(float));

    // walk chain
    k_gather<<<BB, 256>>>(step_memory, query_idx, query_mask);
    dim3 mg(8, BB);
    k_matvec<<<mg, 256>>>(step_memory, pw1, pw2);            // w2 = w1 @ step
    k_matvec<<<mg, 256>>>(step_memory, pw2, pw3);            // w3 = w2 @ step
    k_wsum<<<256, 256>>>(query_idx, query_mask);             // wsum
    k_matvec<<<mg, 256>>>(map_memory, pwsum, paccv);         // acc_values

    // gs = wsum@symbol_bank + accv@value_bank   (z-paired, both into pgs)
    dim3 g1(16, 8, 2);
    k_gemm<8><<<g1, 256>>>(pwsum, paccv, symbol_bank, value_bank,
                           pgs, pgs, SS, DD, SS);
    // hpre = [gs@Wo1 | gs@Wf1]
    dim3 g2(16, 8, 2);
    k_gemm<8><<<g2, 256>>>(pgs, pgs, Wo1, Wf1,
                           phpre, phpre + 1024, DD, 2048, DD);
    // h = gelu(hpre + bias)
    k_gelu<<<512, 256>>>(bo1, bf1);
    // out = [ho@Wo2 | hf@Wf2]   (atomic into d_out)
    dim3 g3(16, 8, 2);
    k_gemm<8><<<g3, 256>>>(ph, ph + 1024, Wo2, Wf2,
                           out, out + BB * VV, 2048, 1024, DD);
    // add final biases
    k_bias<<<512, 256>>>(out, bo2, bf2);
}